// round 9
// baseline (speedup 1.0000x reference)
#include <cuda_runtime.h>
#include <cstdint>

// Problem constants (fixed by setup_inputs)
#define BB 4
#define CC 128
#define HH 96
#define WW 160
#define RR 4
#define SS 17   // 1 + 4*R

// Tiling
#define TW 32
#define TH 8
#define BX 16          // threads in w (2 px each)
#define BY 8
#define NTHREADS (BX * BY)   // 128
#define HALO_W (TW + 2 * RR) // 40
#define HALO_H (TH + 2 * RR) // 16
#define HALO_N (HALO_H * HALO_W)  // 640 floats per channel
#define HALO_P (HALO_N / 2)       // 320 float2 pairs
#define HALO_PW (HALO_W / 2)      // 20 pairs per row

#define NCHUNK 8
#define CPK (CC / NCHUNK)    // 16 channels per chunk
#define STAGE_CH 4           // channels per pipeline stage
#define NSTAGE (CPK / STAGE_CH)  // 4 stages
#define HW (HH * WW)

// packed f32x2 fma: acc = a*b + acc
__device__ __forceinline__ void ffma2(uint64_t& acc, uint64_t a, uint64_t b) {
    asm("fma.rn.f32x2 %0, %1, %2, %0;" : "+l"(acc) : "l"(a), "l"(b));
}
__device__ __forceinline__ uint64_t pack2(float lo, float hi) {
    uint64_t r;
    asm("mov.b64 %0, {%1, %2};" : "=l"(r) : "f"(lo), "f"(hi));
    return r;
}
__device__ __forceinline__ void cp_async8(uint32_t saddr, const void* gaddr, int sz) {
    asm volatile("cp.async.ca.shared.global [%0], [%1], 8, %2;"
                 :: "r"(saddr), "l"(gaddr), "r"(sz) : "memory");
}

__global__ __launch_bounds__(NTHREADS, 8)
void cost_volume_kernel(const float* __restrict__ src,
                        const float* __restrict__ tgt,
                        float* __restrict__ out) {
    // tgt halo double buffer: 2 * 4 * 640 * 4B = 20 KB
    __shared__ float smT[2][STAGE_CH * HALO_N];
    // src pixel-pair double buffer: 2 * 4 * 128 * 8B = 8 KB
    __shared__ uint64_t smS[2][STAGE_CH][NTHREADS];

    const int tx = threadIdx.x;
    const int ty = threadIdx.y;
    const int tid = ty * BX + tx;
    const int w0 = blockIdx.x * TW;
    const int h0 = blockIdx.y * TH;
    const int b     = blockIdx.z >> 3;   // NCHUNK = 8
    const int chunk = blockIdx.z & 7;
    const int c0 = chunk * CPK;
    const int lx = 2 * tx;
    const int w  = w0 + lx;
    const int h  = h0 + ty;

    const float* tgtb = tgt + ((long long)b * CC + c0) * HW;
    const float* srcp = src + (((long long)b * CC + c0) * HH + h) * WW + w;

    // staging offsets (channel-invariant): 320 pairs / 128 threads -> 3 slots
    int goff[3], szv[3];
#pragma unroll
    for (int k = 0; k < 3; k++) {
        int pos2 = tid + k * NTHREADS;      // pair index
        int r    = pos2 / HALO_PW;
        int c2   = pos2 - r * HALO_PW;
        int gr   = h0 - RR + r;
        int gc   = w0 - RR + 2 * c2;        // pair fully in or fully out
        bool ok  = ((unsigned)gr < (unsigned)HH) & ((unsigned)gc < (unsigned)WW);
        goff[k] = gr * WW + gc;
        szv[k]  = ok ? 8 : 0;
    }
    const uint32_t stbase = (uint32_t)__cvta_generic_to_shared(&smT[0][0]);
    const uint32_t ssbase = (uint32_t)__cvta_generic_to_shared(&smS[0][0][0]);
    const bool k2on = tid < HALO_P - 2 * NTHREADS;   // slot 2 active for tid<64

    // stage loader: stage st -> buffer st&1, channels [st*4, st*4+4)
    auto stage_load = [&](int st) {
        const int buf = st & 1;
        const uint32_t sb = stbase + buf * (STAGE_CH * HALO_N * 4);
        const float* tb = tgtb + st * STAGE_CH * HW;
        const float* sp = srcp + st * STAGE_CH * HW;
        const uint32_t ss = ssbase + buf * (STAGE_CH * NTHREADS * 8) + tid * 8;
#pragma unroll
        for (int ch = 0; ch < STAGE_CH; ch++) {
            const float* tc = tb + ch * HW;
            const uint32_t sc = sb + ch * (HALO_N * 4);
            cp_async8(sc + tid * 8,                  tc + goff[0], szv[0]);
            cp_async8(sc + (tid + NTHREADS) * 8,     tc + goff[1], szv[1]);
            if (k2on)
                cp_async8(sc + (tid + 2 * NTHREADS) * 8, tc + goff[2], szv[2]);
            // src pixel pair for this channel (always in-bounds)
            cp_async8(ss + ch * (NTHREADS * 8), sp + ch * HW, 8);
        }
        asm volatile("cp.async.commit_group;" ::: "memory");
    };

    stage_load(0);

    uint64_t acc[SS];
#pragma unroll
    for (int s = 0; s < SS; s++) acc[s] = 0ull;

    const int rowbase = (ty + RR) * HALO_W + lx;

#pragma unroll
    for (int st = 0; st < NSTAGE; st++) {
        if (st + 1 < NSTAGE) {
            stage_load(st + 1);
            asm volatile("cp.async.wait_group 1;" ::: "memory");
        } else {
            asm volatile("cp.async.wait_group 0;" ::: "memory");
        }
        __syncthreads();

        const int buf = st & 1;
        const float* smb = &smT[buf][0];
#pragma unroll
        for (int ch = 0; ch < STAGE_CH; ch++) {
            const uint64_t sv = smS[buf][ch][tid];

            const float* smc = smb + ch * HALO_N;
            float2 t0 = *(const float2*)(smc + rowbase + 0);
            float2 t1 = *(const float2*)(smc + rowbase + 2);
            float2 t2 = *(const float2*)(smc + rowbase + 4);
            float2 t3 = *(const float2*)(smc + rowbase + 6);
            float2 t4 = *(const float2*)(smc + rowbase + 8);

            ffma2(acc[0],  sv, pack2(t2.x, t2.y));
            ffma2(acc[3],  sv, pack2(t1.y, t2.x));
            ffma2(acc[4],  sv, pack2(t2.y, t3.x));
            ffma2(acc[7],  sv, pack2(t1.x, t1.y));
            ffma2(acc[8],  sv, pack2(t3.x, t3.y));
            ffma2(acc[11], sv, pack2(t0.y, t1.x));
            ffma2(acc[12], sv, pack2(t3.y, t4.x));
            ffma2(acc[15], sv, pack2(t0.x, t0.y));
            ffma2(acc[16], sv, pack2(t4.x, t4.y));

#pragma unroll
            for (int i2 = 1; i2 <= RR; i2++) {
                uint64_t tu = *(const uint64_t*)(smc + (ty + RR - i2) * HALO_W + lx + RR);
                uint64_t td = *(const uint64_t*)(smc + (ty + RR + i2) * HALO_W + lx + RR);
                ffma2(acc[4 * i2 - 3], sv, tu);
                ffma2(acc[4 * i2 - 2], sv, td);
            }
        }
        __syncthreads();   // buffer reuse fence before next stage overwrite
    }

    // combine partials across chunks via float2 atomics (no return -> RED)
    float* ob = out + ((((long long)b * SS) * HH) + h) * WW + w;
#pragma unroll
    for (int s = 0; s < SS; s++) {
        float2 o;
        asm("mov.b64 {%0, %1}, %2;" : "=f"(o.x), "=f"(o.y) : "l"(acc[s]));
        atomicAdd((float2*)(ob + s * HW), o);
    }
}

extern "C" void kernel_launch(void* const* d_in, const int* in_sizes, int n_in,
                              void* d_out, int out_size) {
    const float* src = (const float*)d_in[0];
    const float* tgt = (const float*)d_in[1];
    float* out = (float*)d_out;

    cudaMemsetAsync(out, 0, (size_t)out_size * sizeof(float), 0);

    dim3 block(BX, BY);
    dim3 grid(WW / TW, HH / TH, BB * NCHUNK);   // 5 x 12 x 32 = 1920 CTAs
    cost_volume_kernel<<<grid, block>>>(src, tgt, out);
}

// round 10
// speedup vs baseline: 1.0062x; 1.0062x over previous
#include <cuda_runtime.h>
#include <cstdint>

// Problem constants (fixed by setup_inputs)
#define BB 4
#define CC 128
#define HH 96
#define WW 160
#define RR 4
#define SS 17   // 1 + 4*R

// Tiling
#define TW 32
#define TH 8
#define BX 16          // threads in w (2 px each)
#define BY 8
#define NTHREADS (BX * BY)   // 128
#define HALO_W (TW + 2 * RR) // 40
#define HALO_H (TH + 2 * RR) // 16
#define HALO_N (HALO_H * HALO_W)  // 640 floats per channel
#define HALO_P (HALO_N / 2)       // 320 float2 pairs
#define HALO_PW (HALO_W / 2)      // 20 pairs per row

#define NCHUNK 16
#define CPK (CC / NCHUNK)    // 8 channels per chunk
#define HW (HH * WW)

// packed f32x2 fma: acc = a*b + acc
__device__ __forceinline__ void ffma2(uint64_t& acc, uint64_t a, uint64_t b) {
    asm("fma.rn.f32x2 %0, %1, %2, %0;" : "+l"(acc) : "l"(a), "l"(b));
}
__device__ __forceinline__ uint64_t pack2(float lo, float hi) {
    uint64_t r;
    asm("mov.b64 %0, {%1, %2};" : "=l"(r) : "f"(lo), "f"(hi));
    return r;
}
__device__ __forceinline__ void cp_async8(uint32_t saddr, const void* gaddr, int sz) {
    asm volatile("cp.async.ca.shared.global [%0], [%1], 8, %2;"
                 :: "r"(saddr), "l"(gaddr), "r"(sz) : "memory");
}
__device__ __forceinline__ void red_add_f2(float* p, uint64_t v) {
    float2 o;
    asm("mov.b64 {%0, %1}, %2;" : "=f"(o.x), "=f"(o.y) : "l"(v));
    atomicAdd((float2*)p, o);
}

__global__ __launch_bounds__(NTHREADS, 10)
void cost_volume_kernel(const float* __restrict__ src,
                        const float* __restrict__ tgt,
                        float* __restrict__ out) {
    __shared__ float sm[CPK * HALO_N];   // 8 * 640 * 4B = 20 KB

    const int tx = threadIdx.x;
    const int ty = threadIdx.y;
    const int tid = ty * BX + tx;
    const int w0 = blockIdx.x * TW;
    const int h0 = blockIdx.y * TH;
    const int b     = blockIdx.z >> 4;   // NCHUNK = 16
    const int chunk = blockIdx.z & 15;
    const int c0 = chunk * CPK;
    const int lx = 2 * tx;
    const int w  = w0 + lx;
    const int h  = h0 + ty;

    const float* tgtb = tgt + ((long long)b * CC + c0) * HW;
    const float* srcp = src + (((long long)b * CC + c0) * HH + h) * WW + w;

    // ---- single-shot staging of CPK channels via cp.async ----
    {
        int goff[3], szv[3];
#pragma unroll
        for (int k = 0; k < 3; k++) {
            int pos2 = tid + k * NTHREADS;   // pair index
            int r    = pos2 / HALO_PW;
            int c2   = pos2 - r * HALO_PW;
            int gr   = h0 - RR + r;
            int gc   = w0 - RR + 2 * c2;     // pair fully in or fully out
            bool ok  = ((unsigned)gr < (unsigned)HH) & ((unsigned)gc < (unsigned)WW);
            goff[k] = gr * WW + gc;
            szv[k]  = ok ? 8 : 0;
        }
        const uint32_t sbase = (uint32_t)__cvta_generic_to_shared(sm);
        const bool k2on = tid < HALO_P - 2 * NTHREADS;
#pragma unroll
        for (int ch = 0; ch < CPK; ch++) {
            const float* tc = tgtb + ch * HW;
            const uint32_t sc = sbase + ch * (HALO_N * 4);
            cp_async8(sc + tid * 8,                  tc + goff[0], szv[0]);
            cp_async8(sc + (tid + NTHREADS) * 8,     tc + goff[1], szv[1]);
            if (k2on)
                cp_async8(sc + (tid + 2 * NTHREADS) * 8, tc + goff[2], szv[2]);
        }
        asm volatile("cp.async.commit_group;" ::: "memory");
        asm volatile("cp.async.wait_group 0;" ::: "memory");
    }
    __syncthreads();

    const int rowbase = (ty + RR) * HALO_W + lx;
    float* ob = out + ((((long long)b * SS) * HH) + h) * WW + w;

    // ================= PASS A: horizontal shifts (9 accumulators) =============
    {
        uint64_t acc[9];   // s = 0, 3,4, 7,8, 11,12, 15,16
#pragma unroll
        for (int k = 0; k < 9; k++) acc[k] = 0ull;

        uint64_t sv0 = *(const uint64_t*)(srcp);
        uint64_t sv1 = *(const uint64_t*)(srcp + HW);
#pragma unroll
        for (int ch = 0; ch < CPK; ch++) {
            uint64_t sv = sv0;
            sv0 = sv1;
            if (ch + 2 < CPK) sv1 = *(const uint64_t*)(srcp + (ch + 2) * HW);

            const float* smc = sm + ch * HALO_N;
            float2 t0 = *(const float2*)(smc + rowbase + 0);
            float2 t1 = *(const float2*)(smc + rowbase + 2);
            float2 t2 = *(const float2*)(smc + rowbase + 4);
            float2 t3 = *(const float2*)(smc + rowbase + 6);
            float2 t4 = *(const float2*)(smc + rowbase + 8);

            ffma2(acc[0], sv, pack2(t2.x, t2.y));   // s=0
            ffma2(acc[1], sv, pack2(t1.y, t2.x));   // s=3  (0,-1)
            ffma2(acc[2], sv, pack2(t2.y, t3.x));   // s=4  (0,+1)
            ffma2(acc[3], sv, pack2(t1.x, t1.y));   // s=7  (0,-2)
            ffma2(acc[4], sv, pack2(t3.x, t3.y));   // s=8  (0,+2)
            ffma2(acc[5], sv, pack2(t0.y, t1.x));   // s=11 (0,-3)
            ffma2(acc[6], sv, pack2(t3.y, t4.x));   // s=12 (0,+3)
            ffma2(acc[7], sv, pack2(t0.x, t0.y));   // s=15 (0,-4)
            ffma2(acc[8], sv, pack2(t4.x, t4.y));   // s=16 (0,+4)
        }
        // emit horizontal atomics now -> frees 18 regs before pass B
        red_add_f2(ob + 0  * HW, acc[0]);
        red_add_f2(ob + 3  * HW, acc[1]);
        red_add_f2(ob + 4  * HW, acc[2]);
        red_add_f2(ob + 7  * HW, acc[3]);
        red_add_f2(ob + 8  * HW, acc[4]);
        red_add_f2(ob + 11 * HW, acc[5]);
        red_add_f2(ob + 12 * HW, acc[6]);
        red_add_f2(ob + 15 * HW, acc[7]);
        red_add_f2(ob + 16 * HW, acc[8]);
    }

    // ================= PASS B: vertical shifts (8 accumulators) ===============
    {
        uint64_t acc[8];   // s = 1,2, 5,6, 9,10, 13,14  (up i / down i)
#pragma unroll
        for (int k = 0; k < 8; k++) acc[k] = 0ull;

        const int vb = lx + RR;   // center column pair
        uint64_t sv0 = *(const uint64_t*)(srcp);
        uint64_t sv1 = *(const uint64_t*)(srcp + HW);
#pragma unroll
        for (int ch = 0; ch < CPK; ch++) {
            uint64_t sv = sv0;
            sv0 = sv1;
            if (ch + 2 < CPK) sv1 = *(const uint64_t*)(srcp + (ch + 2) * HW);

            const float* vc = sm + ch * HALO_N + vb;
#pragma unroll
            for (int i2 = 1; i2 <= RR; i2++) {
                uint64_t tu = *(const uint64_t*)(vc + (ty + RR - i2) * HALO_W);
                uint64_t td = *(const uint64_t*)(vc + (ty + RR + i2) * HALO_W);
                ffma2(acc[2 * i2 - 2], sv, tu);   // s = 4i-3
                ffma2(acc[2 * i2 - 1], sv, td);   // s = 4i-2
            }
        }
#pragma unroll
        for (int i2 = 1; i2 <= RR; i2++) {
            red_add_f2(ob + (4 * i2 - 3) * HW, acc[2 * i2 - 2]);
            red_add_f2(ob + (4 * i2 - 2) * HW, acc[2 * i2 - 1]);
        }
    }
}

extern "C" void kernel_launch(void* const* d_in, const int* in_sizes, int n_in,
                              void* d_out, int out_size) {
    const float* src = (const float*)d_in[0];
    const float* tgt = (const float*)d_in[1];
    float* out = (float*)d_out;

    cudaMemsetAsync(out, 0, (size_t)out_size * sizeof(float), 0);

    dim3 block(BX, BY);
    dim3 grid(WW / TW, HH / TH, BB * NCHUNK);   // 5 x 12 x 64 = 3840 CTAs
    cost_volume_kernel<<<grid, block>>>(src, tgt, out);
}